// round 2
// baseline (speedup 1.0000x reference)
#include <cuda_runtime.h>
#include <cstdint>

// AggrSum: out[n, :] = sum over edges e with X_node[e] == n of H[e, :]
// H: [NUM_EDGES, 32] float32, X_node: [NUM_EDGES] int32 (harness downcasts
// the reference's int64 -> int32), out: [node_num, 32] float32
//
// Strategy: zero output, then vectorized scatter-add with red.global.add.v4.f32
// (no-return REDG path; RMW resolves at L2, and out (12.8 MB) fits in L2).

static constexpr int D = 32;           // feature dim
static constexpr int VEC = 4;          // float4
static constexpr int LANES = D / VEC;  // 8 threads per edge

__global__ void zero_out_kernel(float4* __restrict__ out, int n4) {
    int i = blockIdx.x * blockDim.x + threadIdx.x;
    if (i < n4) {
        out[i] = make_float4(0.f, 0.f, 0.f, 0.f);
    }
}

__global__ void scatter_add_kernel(const float4* __restrict__ H,
                                   const int* __restrict__ idx,
                                   float* __restrict__ out,
                                   int num_edges, int node_num) {
    int t = blockIdx.x * blockDim.x + threadIdx.x;
    int edge = t >> 3;         // 8 lanes per edge
    int lane = t & 7;
    if (edge >= num_edges) return;

    // Coalesced: consecutive threads read consecutive 16B chunks of H.
    float4 v = __ldg(&H[edge * LANES + lane]);
    int node = __ldg(&idx[edge]);

    // Defensive range check (cheap; avoids crashes if dtype assumption shifts)
    if ((unsigned)node < (unsigned)node_num) {
        float* dst = out + (size_t)node * D + lane * VEC;
        // Vector reduction, no return value (REDG). sm_90+ PTX.
        asm volatile("red.global.add.v4.f32 [%0], {%1, %2, %3, %4};"
                     :: "l"(dst), "f"(v.x), "f"(v.y), "f"(v.z), "f"(v.w)
                     : "memory");
    }
}

extern "C" void kernel_launch(void* const* d_in, const int* in_sizes, int n_in,
                              void* d_out, int out_size) {
    const float4* H = (const float4*)d_in[0];
    const int* idx = (const int*)d_in[1];
    float* out = (float*)d_out;

    int num_edges = in_sizes[0] / D;
    int node_num = out_size / D;

    // 1) zero the output (poisoned to 0xAA by harness)
    int n4 = out_size / VEC;
    {
        int threads = 256;
        int blocks = (n4 + threads - 1) / threads;
        zero_out_kernel<<<blocks, threads>>>((float4*)d_out, n4);
    }

    // 2) scatter-add
    {
        int threads = 256;
        long long total = (long long)num_edges * LANES;
        int blocks = (int)((total + threads - 1) / threads);
        scatter_add_kernel<<<blocks, threads>>>(H, idx, out, num_edges, node_num);
    }
}

// round 3
// speedup vs baseline: 1.2952x; 1.2952x over previous
#include <cuda_runtime.h>
#include <cstdint>

// AggrSum: out[n, :] = sum over edges e with X_node[e] == n of H[e, :]
// H: [NUM_EDGES, 32] f32, X_node: [NUM_EDGES] i32 (harness downcast), out: [node_num, 32] f32
//
// R3: MLP-batched scatter. Each thread handles UNROLL items (item = one float4
// of one edge row), loads front-batched for ~16 outstanding sectors per thread,
// H streamed with evict-first (__ldcs) so L2 stays resident for the atomic
// destination. Reductions via red.global.add.v4.f32 (REDG, no return trip).

static constexpr int D = 32;
static constexpr int VEC = 4;
static constexpr int LANES = D / VEC;   // 8 float4s per edge
static constexpr int UNROLL = 8;
static constexpr int THREADS = 256;

__global__ void zero_out_kernel(float4* __restrict__ out, int n4) {
    int T = gridDim.x * blockDim.x;
    for (int i = blockIdx.x * blockDim.x + threadIdx.x; i < n4; i += T) {
        out[i] = make_float4(0.f, 0.f, 0.f, 0.f);
    }
}

__global__ void __launch_bounds__(THREADS)
scatter_add_kernel(const float4* __restrict__ H,
                   const int* __restrict__ idx,
                   float* __restrict__ out,
                   int nitems, int node_num) {
    const int T = gridDim.x * blockDim.x;
    int t = blockIdx.x * blockDim.x + threadIdx.x;

    for (int base = t; base < nitems; base += T * UNROLL) {
        int   i[UNROLL];
        float4 v[UNROLL];
        int   n[UNROLL];

        // Front-batched H loads: UNROLL independent LDG.128 in flight.
        #pragma unroll
        for (int k = 0; k < UNROLL; k++) {
            i[k] = base + k * T;
            if (i[k] < nitems) v[k] = __ldcs(&H[i[k]]);   // evict-first: pure stream
        }
        // Index loads (8 lanes share an edge -> broadcast within warp).
        #pragma unroll
        for (int k = 0; k < UNROLL; k++) {
            if (i[k] < nitems) n[k] = __ldcs(&idx[i[k] >> 3]);
        }
        // Fire-and-forget vector reductions (resolve at L2; out stays resident).
        #pragma unroll
        for (int k = 0; k < UNROLL; k++) {
            if (i[k] < nitems && (unsigned)n[k] < (unsigned)node_num) {
                float* dst = out + (size_t)n[k] * D + (i[k] & (LANES - 1)) * VEC;
                asm volatile("red.global.add.v4.f32 [%0], {%1, %2, %3, %4};"
                             :: "l"(dst), "f"(v[k].x), "f"(v[k].y), "f"(v[k].z), "f"(v[k].w)
                             : "memory");
            }
        }
    }
}

extern "C" void kernel_launch(void* const* d_in, const int* in_sizes, int n_in,
                              void* d_out, int out_size) {
    const float4* H = (const float4*)d_in[0];
    const int* idx = (const int*)d_in[1];
    float* out = (float*)d_out;

    int num_edges = in_sizes[0] / D;
    int node_num = out_size / D;
    int nitems = num_edges * LANES;           // 16M float4 items

    // 1) zero output (poisoned to 0xAA). 12.8 MB -> ~2-3 us.
    {
        int n4 = out_size / VEC;
        int blocks = (n4 + THREADS - 1) / THREADS;
        if (blocks > 2048) blocks = 2048;
        zero_out_kernel<<<blocks, THREADS>>>((float4*)d_out, n4);
    }

    // 2) scatter-add: size grid so each thread does exactly one UNROLL batch.
    {
        long long want = ((long long)nitems + UNROLL - 1) / UNROLL;  // threads needed
        int blocks = (int)((want + THREADS - 1) / THREADS);
        scatter_add_kernel<<<blocks, THREADS>>>(H, idx, out, nitems, node_num);
    }
}

// round 4
// speedup vs baseline: 1.3014x; 1.0048x over previous
#include <cuda_runtime.h>
#include <cstdint>

// AggrSum: out[n, :] = sum over edges e with X_node[e] == n of H[e, :]
// H: [2M, 32] f32, X_node: [2M] i32 (harness downcast), out: [100K, 32] f32
//
// R4: register-dieted MLP-batched scatter. 128-thread blocks, exact tiling
// (grid*block*UNROLL == nitems for the expected shape -> predicate-free hot
// path), 8 front-batched LDG.128 per thread, REDG v4 scatter (resolves in L2).

static constexpr int D = 32;
static constexpr int VEC = 4;
static constexpr int LANES = D / VEC;   // 8 float4s per edge
static constexpr int UNROLL = 8;
static constexpr int THREADS = 128;

__global__ void zero_out_kernel(float4* __restrict__ out, int n4) {
    int T = gridDim.x * blockDim.x;
    for (int i = blockIdx.x * blockDim.x + threadIdx.x; i < n4; i += T) {
        out[i] = make_float4(0.f, 0.f, 0.f, 0.f);
    }
}

__device__ __forceinline__ void red_add_v4(float* dst, float4 v) {
    asm volatile("red.global.add.v4.f32 [%0], {%1, %2, %3, %4};"
                 :: "l"(dst), "f"(v.x), "f"(v.y), "f"(v.z), "f"(v.w)
                 : "memory");
}

__global__ void __launch_bounds__(THREADS)
scatter_add_kernel(const float4* __restrict__ H,
                   const int* __restrict__ idx,
                   float* __restrict__ out,
                   int nitems, int node_num) {
    const int T = gridDim.x * blockDim.x;   // stride between a thread's items
    const int t = blockIdx.x * blockDim.x + threadIdx.x;

    if (t + 7 * T < nitems) {
        // Fast path: all 8 items in range (always taken at the bench shape).
        float4 v[UNROLL];
        int    n[UNROLL];
        #pragma unroll
        for (int k = 0; k < UNROLL; k++)
            v[k] = __ldcs(&H[t + k * T]);            // evict-first stream
        #pragma unroll
        for (int k = 0; k < UNROLL; k++)
            n[k] = __ldg(&idx[(t + k * T) >> 3]);    // broadcast within 8 lanes
        #pragma unroll
        for (int k = 0; k < UNROLL; k++) {
            float* dst = out + (size_t)(unsigned)n[k] * D
                             + ((t + k * T) & (LANES - 1)) * VEC;
            red_add_v4(dst, v[k]);
        }
    } else {
        // Tail path (never taken when nitems % (T*UNROLL) == 0).
        #pragma unroll
        for (int k = 0; k < UNROLL; k++) {
            int i = t + k * T;
            if (i < nitems) {
                float4 v = __ldcs(&H[i]);
                int n = __ldg(&idx[i >> 3]);
                if ((unsigned)n < (unsigned)node_num) {
                    float* dst = out + (size_t)(unsigned)n * D + (i & (LANES - 1)) * VEC;
                    red_add_v4(dst, v);
                }
            }
        }
    }
}

extern "C" void kernel_launch(void* const* d_in, const int* in_sizes, int n_in,
                              void* d_out, int out_size) {
    const float4* H = (const float4*)d_in[0];
    const int* idx = (const int*)d_in[1];
    float* out = (float*)d_out;

    int num_edges = in_sizes[0] / D;
    int node_num = out_size / D;
    int nitems = num_edges * LANES;   // 16,000,000 float4 items at bench shape

    // 1) zero output (poisoned to 0xAA). 12.8 MB.
    {
        int n4 = out_size / VEC;
        int blocks = (n4 + 255) / 256;
        if (blocks > 3200) blocks = 3200;
        zero_out_kernel<<<blocks, 256>>>((float4*)d_out, n4);
    }

    // 2) scatter-add: exact cover -> predicate-free hot path.
    {
        long long want = ((long long)nitems + UNROLL - 1) / UNROLL;  // threads
        int blocks = (int)((want + THREADS - 1) / THREADS);          // 15625 exact
        scatter_add_kernel<<<blocks, THREADS>>>(H, idx, out, nitems, node_num);
    }
}